// round 14
// baseline (speedup 1.0000x reference)
#include <cuda_runtime.h>
#include <cuda_fp16.h>
#include <cstddef>

#define D_MODEL 1024
#define NUM_HEADS 16
#define DEPTH 64
#define BATCH 4
#define SEQ 2048
#define BHN (BATCH * NUM_HEADS)
#define BQ 128
#define KBB 128
#define NKB (SEQ / KBB)         // 16
#define QSTR 72
#define GSTR 40
#define MTOT (BATCH * SEQ)      // 8192
#define QSCALE 0.18033688011112042f   // 0.125 * log2(e)
#define MSCALE (-1.4426950408889634e9f) // -1e9 * log2(e)

// Scratch (device globals; no allocation allowed)
__device__ __half g_Q[(size_t)BHN * SEQ * DEPTH];
__device__ __half g_K[(size_t)BHN * SEQ * DEPTH];
__device__ __half g_V[(size_t)BHN * SEQ * DEPTH];
__device__ __half g_CTX[(size_t)BATCH * SEQ * D_MODEL];
__device__ __half g_XH[3][(size_t)MTOT * D_MODEL];
__device__ __half g_WH[4][(size_t)D_MODEL * D_MODEL];
__device__ float  g_MT[(size_t)SEQ * SEQ];          // mask * (-1e9*log2e)

// ---------------------------------------------------------------------------
// Helpers
// ---------------------------------------------------------------------------
__device__ __forceinline__ unsigned pack2(float a, float b) {
    __half2 h = __floats2half2_rn(a, b);
    return *(unsigned*)&h;
}
__device__ __forceinline__ float ex2(float x) {
    float r; asm("ex2.approx.ftz.f32 %0, %1;" : "=f"(r) : "f"(x)); return r;
}
__device__ __forceinline__ float lg2(float x) {
    float r; asm("lg2.approx.f32 %0, %1;" : "=f"(r) : "f"(x)); return r;
}

__device__ __forceinline__ void mma16(float* d, const unsigned* a, const unsigned* b) {
    asm volatile(
        "mma.sync.aligned.m16n8k16.row.col.f32.f16.f16.f32 "
        "{%0,%1,%2,%3}, {%4,%5,%6,%7}, {%8,%9}, {%0,%1,%2,%3};\n"
        : "+f"(d[0]), "+f"(d[1]), "+f"(d[2]), "+f"(d[3])
        : "r"(a[0]), "r"(a[1]), "r"(a[2]), "r"(a[3]), "r"(b[0]), "r"(b[1]));
}

__device__ __forceinline__ void ldsm_x4(unsigned& r0, unsigned& r1,
                                        unsigned& r2, unsigned& r3, unsigned addr) {
    asm volatile("ldmatrix.sync.aligned.m8n8.x4.shared.b16 {%0,%1,%2,%3}, [%4];"
                 : "=r"(r0), "=r"(r1), "=r"(r2), "=r"(r3) : "r"(addr));
}
__device__ __forceinline__ void ldsm_x4_t(unsigned& r0, unsigned& r1,
                                          unsigned& r2, unsigned& r3, unsigned addr) {
    asm volatile("ldmatrix.sync.aligned.m8n8.x4.trans.shared.b16 {%0,%1,%2,%3}, [%4];"
                 : "=r"(r0), "=r"(r1), "=r"(r2), "=r"(r3) : "r"(addr));
}

__device__ __forceinline__ void cp16(unsigned smem_addr, const void* gptr) {
    asm volatile("cp.async.cg.shared.global [%0], [%1], 16;"
                 :: "r"(smem_addr), "l"(gptr));
}
__device__ __forceinline__ void cp_commit() { asm volatile("cp.async.commit_group;"); }
__device__ __forceinline__ void cp_wait0()  { asm volatile("cp.async.wait_group 0;"); }
__device__ __forceinline__ void cp_wait1()  { asm volatile("cp.async.wait_group 1;"); }

// ---------------------------------------------------------------------------
// Convert fp32 -> half (inputs + weights), and mask -> scaled fp32.
// ---------------------------------------------------------------------------
struct ConvJobs {
    const float* src[7];
    __half* dst[7];
    int n[7];
};

__global__ void __launch_bounds__(256)
convert_f2h(ConvJobs jobs)
{
    const int z = blockIdx.z;
    const float* s = jobs.src[z];
    __half* d = jobs.dst[z];
    const int n = jobs.n[z];
    for (int i = (blockIdx.x * 256 + threadIdx.x) * 4; i < n; i += gridDim.x * 256 * 4) {
        float4 v = *(const float4*)(s + i);
        *(uint2*)(d + i) = make_uint2(pack2(v.x, v.y), pack2(v.z, v.w));
    }
}

__global__ void __launch_bounds__(256)
scale_mask(const float* __restrict__ mask, float* __restrict__ mt, int n)
{
    for (int i = (blockIdx.x * 256 + threadIdx.x) * 4; i < n; i += gridDim.x * 256 * 4) {
        float4 v = *(const float4*)(mask + i);
        v.x *= MSCALE; v.y *= MSCALE; v.z *= MSCALE; v.w *= MSCALE;
        *(float4*)(mt + i) = v;
    }
}

// ---------------------------------------------------------------------------
// GEMM: C = (A(MxK) @ W(NxK)^T + bias) * oscale  (half operands, fp32 accum,
// ldmatrix fragments, 3-stage cp.async pipeline, dynamic smem).
// ---------------------------------------------------------------------------
template <int HEADMAJOR, typename TO>
__global__ void __launch_bounds__(256, 2)
gemm_f16(const __half* __restrict__ A, const __half* __restrict__ W,
         const float* __restrict__ bias, TO* __restrict__ C,
         int M, int N, int K, float oscale)
{
    const int BM = 128, BN = 128, BK = 32;
    extern __shared__ __half gsm[];
    const unsigned stage_bytes = BM * GSTR * 2;        // 10240
    const unsigned as_base = (unsigned)__cvta_generic_to_shared(gsm);
    const unsigned bs_base = as_base + 3 * stage_bytes;

    const int m0 = blockIdx.y * BM;
    const int n0 = blockIdx.x * BN;
    const int t = threadIdx.x;
    const int warp = t >> 5, lane = t & 31;
    const int wm = (warp >> 2) * 64, wn = (warp & 3) * 32;
    const int gid = lane >> 2, tig = lane & 3;

    const int mtx = lane >> 3;
    const int mrr = lane & 7;
    const int a_roff = (mtx & 1) * 8;
    const int a_koff = (mtx >> 1) * 8;
    const int ni_off = mtx >> 1;
    const int kh_off = (mtx & 1) * 8;

    // staging: 128 rows x 32 halves; 2 threads/row sc in {0,16}
    const int sr = t >> 1;
    const int sc = (t & 1) << 4;

    auto stage = [&](int kt, int b) {
        const __half* Ab = A + (size_t)(m0 + sr) * K + kt * BK + sc;
        const __half* Wb = W + (size_t)(n0 + sr) * K + kt * BK + sc;
        unsigned ao = as_base + b * stage_bytes + (unsigned)((sr * GSTR + sc) * 2);
        unsigned bo = bs_base + b * stage_bytes + (unsigned)((sr * GSTR + sc) * 2);
        cp16(ao,      Ab);
        cp16(ao + 16, Ab + 8);
        cp16(bo,      Wb);
        cp16(bo + 16, Wb + 8);
    };

    float acc[4][4][4];
#pragma unroll
    for (int mi = 0; mi < 4; mi++)
#pragma unroll
        for (int ni = 0; ni < 4; ni++)
#pragma unroll
            for (int r = 0; r < 4; r++) acc[mi][ni][r] = 0.f;

    const int NKT = K / BK;
    stage(0, 0); cp_commit();
    stage(1, 1); cp_commit();

    for (int kt = 0; kt < NKT; kt++) {
        if (kt < NKT - 1) cp_wait1(); else cp_wait0();
        __syncthreads();
        if (kt + 2 < NKT) { stage(kt + 2, (kt + 2) % 3); cp_commit(); }

        const int buf = kt % 3;
#pragma unroll
        for (int ks = 0; ks < BK; ks += 16) {
            unsigned af[4][4], bf[4][2];
#pragma unroll
            for (int mi = 0; mi < 4; mi++) {
                unsigned addr = as_base + buf * stage_bytes +
                    (unsigned)(((wm + mi * 16 + a_roff + mrr) * GSTR + ks + a_koff) * 2);
                ldsm_x4(af[mi][0], af[mi][1], af[mi][2], af[mi][3], addr);
            }
#pragma unroll
            for (int i = 0; i < 2; i++) {
                unsigned addr = bs_base + buf * stage_bytes +
                    (unsigned)(((wn + (2 * i + ni_off) * 8 + mrr) * GSTR + ks + kh_off) * 2);
                ldsm_x4(bf[2 * i][0], bf[2 * i][1], bf[2 * i + 1][0], bf[2 * i + 1][1], addr);
            }
#pragma unroll
            for (int mi = 0; mi < 4; mi++)
#pragma unroll
                for (int ni = 0; ni < 4; ni++)
                    mma16(acc[mi][ni], af[mi], bf[ni]);
        }
        __syncthreads();
    }

#pragma unroll
    for (int mi = 0; mi < 4; mi++) {
        int r0 = m0 + wm + mi * 16 + gid;
#pragma unroll
        for (int ni = 0; ni < 4; ni++) {
            int c0 = n0 + wn + ni * 8 + 2 * tig;
            float b0 = bias[c0], b1 = bias[c0 + 1];
            float v0 = (acc[mi][ni][0] + b0) * oscale;
            float v1 = (acc[mi][ni][1] + b1) * oscale;
            float v2 = (acc[mi][ni][2] + b0) * oscale;
            float v3 = (acc[mi][ni][3] + b1) * oscale;
            if constexpr (HEADMAJOR) {
                int h = c0 >> 6, d = c0 & (DEPTH - 1);
                {
                    int m = r0;
                    int bb = m >> 11, s = m & (SEQ - 1);
                    __half* dst = (__half*)C +
                        (((size_t)(bb * NUM_HEADS + h)) * SEQ + s) * DEPTH + d;
                    *(unsigned*)dst = pack2(v0, v1);
                }
                {
                    int m = r0 + 8;
                    int bb = m >> 11, s = m & (SEQ - 1);
                    __half* dst = (__half*)C +
                        (((size_t)(bb * NUM_HEADS + h)) * SEQ + s) * DEPTH + d;
                    *(unsigned*)dst = pack2(v2, v3);
                }
            } else {
                float* dst = (float*)C;
                *(float2*)&dst[(size_t)r0 * N + c0]       = make_float2(v0, v1);
                *(float2*)&dst[(size_t)(r0 + 8) * N + c0] = make_float2(v2, v3);
            }
        }
    }
}

// ---------------------------------------------------------------------------
// Fused attention: base-2 softmax folding. Q pre-scaled by 0.125*log2e,
// mask term pre-scaled by -1e9*log2e. Pass A: s2 = acc + mt; stats m,l.
// Pass B: z = m + log2(l); p = ex2(s2 - z). Single MUFU per element.
// ---------------------------------------------------------------------------
__global__ void __launch_bounds__(256, 2)
fused_attn(const __half* __restrict__ Q, const __half* __restrict__ Kmat,
           const __half* __restrict__ V, const float* __restrict__ mt,
           float* __restrict__ attn, __half* __restrict__ ctx)
{
    extern __shared__ __half dsm[];
    const unsigned ks_base = (unsigned)__cvta_generic_to_shared(dsm);
    const unsigned vs_base = ks_base + 2 * KBB * QSTR * 2;
    const unsigned buf_stride = KBB * QSTR * 2;

    const int bh = blockIdx.y;
    const int q0 = blockIdx.x * BQ;
    const __half* Qb = Q    + (size_t)bh * SEQ * DEPTH;
    const __half* Kb = Kmat + (size_t)bh * SEQ * DEPTH;
    const __half* Vb = V    + (size_t)bh * SEQ * DEPTH;
    float* attnb = attn + (size_t)bh * SEQ * SEQ;

    const int t = threadIdx.x;
    const int warp = t >> 5, lane = t & 31;
    const int gid = lane >> 2, tig = lane & 3;
    const int r0 = warp * 16 + gid;
    const int r1 = r0 + 8;

    const int mtx = lane >> 3;
    const int mrr = lane & 7;
    const int ni_off = mtx >> 1;
    const int kh_off = (mtx & 1) * 8;

    const int sr = t >> 1;
    const int sc = (t & 1) << 5;           // 0 / 32

    auto stageK = [&](int kb, int b) {
        const __half* g = Kb + (size_t)(kb * KBB + sr) * DEPTH + sc;
        unsigned o = ks_base + b * buf_stride + (unsigned)((sr * QSTR + sc) * 2);
        cp16(o, g); cp16(o + 16, g + 8);
        cp16(o + 32, g + 16); cp16(o + 48, g + 24);
    };
    auto stageV = [&](int kb, int b) {
        const __half* g = Vb + (size_t)(kb * KBB + sr) * DEPTH + sc;
        unsigned o = vs_base + b * buf_stride + (unsigned)((sr * QSTR + sc) * 2);
        cp16(o, g); cp16(o + 16, g + 8);
        cp16(o + 32, g + 16); cp16(o + 48, g + 24);
    };

    // Q fragments in registers (Q already scaled by 0.125*log2e)
    unsigned qf[4][4];
#pragma unroll
    for (int s = 0; s < 4; s++) {
        qf[s][0] = *(const unsigned*)&Qb[(size_t)(q0 + r0) * DEPTH + 16 * s + 2 * tig];
        qf[s][1] = *(const unsigned*)&Qb[(size_t)(q0 + r1) * DEPTH + 16 * s + 2 * tig];
        qf[s][2] = *(const unsigned*)&Qb[(size_t)(q0 + r0) * DEPTH + 16 * s + 8 + 2 * tig];
        qf[s][3] = *(const unsigned*)&Qb[(size_t)(q0 + r1) * DEPTH + 16 * s + 8 + 2 * tig];
    }

    const float* mrow0 = mt + (size_t)(q0 + r0) * SEQ;
    const float* mrow1 = mt + (size_t)(q0 + r1) * SEQ;

    float m0 = -1e30f, m1 = -1e30f, l0 = 0.f, l1 = 0.f;

    // ------------------------- Pass A: stats -------------------------
    stageK(0, 0);
    cp_commit();
    int buf = 0;
    for (int kb = 0; kb < NKB; kb++) {
        cp_wait0();
        __syncthreads();
        if (kb + 1 < NKB) { stageK(kb + 1, buf ^ 1); cp_commit(); }

#pragma unroll
        for (int ch = 0; ch < 2; ch++) {
            const int k0 = kb * KBB + ch * 64;
            const int rowoff = buf * KBB + ch * 64;

            float acc[8][4];
#pragma unroll
            for (int ni = 0; ni < 8; ni++)
#pragma unroll
                for (int r = 0; r < 4; r++) acc[ni][r] = 0.f;

#pragma unroll
            for (int s = 0; s < 4; s++) {
                unsigned bf[8][2];
#pragma unroll
                for (int i = 0; i < 4; i++) {
                    unsigned addr = ks_base +
                        (unsigned)(((rowoff + (2 * i + ni_off) * 8 + mrr) * QSTR
                                    + 16 * s + kh_off) * 2);
                    ldsm_x4(bf[2 * i][0], bf[2 * i][1], bf[2 * i + 1][0], bf[2 * i + 1][1], addr);
                }
#pragma unroll
                for (int ni = 0; ni < 8; ni++) mma16(acc[ni], qf[s], bf[ni]);
            }

            float rm0 = -1e30f, rm1 = -1e30f;
#pragma unroll
            for (int ni = 0; ni < 8; ni++) {
                int c = ni * 8 + 2 * tig;
                float2 mv0 = *(const float2*)&mrow0[k0 + c];
                float2 mv1 = *(const float2*)&mrow1[k0 + c];
                acc[ni][0] += mv0.x;
                acc[ni][1] += mv0.y;
                acc[ni][2] += mv1.x;
                acc[ni][3] += mv1.y;
                rm0 = fmaxf(rm0, fmaxf(acc[ni][0], acc[ni][1]));
                rm1 = fmaxf(rm1, fmaxf(acc[ni][2], acc[ni][3]));
            }
            rm0 = fmaxf(rm0, __shfl_xor_sync(0xffffffffu, rm0, 1));
            rm0 = fmaxf(rm0, __shfl_xor_sync(0xffffffffu, rm0, 2));
            rm1 = fmaxf(rm1, __shfl_xor_sync(0xffffffffu, rm1, 1));
            rm1 = fmaxf(rm1, __shfl_xor_sync(0xffffffffu, rm1, 2));

            float mn0 = fmaxf(m0, rm0), mn1 = fmaxf(m1, rm1);
            float sc0 = ex2(m0 - mn0), sc1 = ex2(m1 - mn1);
            m0 = mn0; m1 = mn1;

            float ts0 = 0.f, ts1 = 0.f;
#pragma unroll
            for (int ni = 0; ni < 8; ni++) {
                ts0 += ex2(acc[ni][0] - m0) + ex2(acc[ni][1] - m0);
                ts1 += ex2(acc[ni][2] - m1) + ex2(acc[ni][3] - m1);
            }
            ts0 += __shfl_xor_sync(0xffffffffu, ts0, 1);
            ts0 += __shfl_xor_sync(0xffffffffu, ts0, 2);
            ts1 += __shfl_xor_sync(0xffffffffu, ts1, 1);
            ts1 += __shfl_xor_sync(0xffffffffu, ts1, 2);

            l0 = l0 * sc0 + ts0;
            l1 = l1 * sc1 + ts1;
        }
        __syncthreads();
        buf ^= 1;
    }

    // z = m + log2(l): p = 2^(s2 - z) = 2^(s2-m)/l
    const float z0 = m0 + lg2(l0);
    const float z1 = m1 + lg2(l1);

    // ------------------------- Pass B: write + PV -------------------------
    float cacc[8][4];
#pragma unroll
    for (int ni = 0; ni < 8; ni++)
#pragma unroll
        for (int r = 0; r < 4; r++) cacc[ni][r] = 0.f;

    stageK(0, 0); stageV(0, 0);
    cp_commit();
    buf = 0;
    for (int kb = 0; kb < NKB; kb++) {
        cp_wait0();
        __syncthreads();
        if (kb + 1 < NKB) { stageK(kb + 1, buf ^ 1); stageV(kb + 1, buf ^ 1); cp_commit(); }

#pragma unroll
        for (int ch = 0; ch < 2; ch++) {
            const int k0 = kb * KBB + ch * 64;
            const int rowoff = buf * KBB + ch * 64;

            float acc[8][4];
#pragma unroll
            for (int ni = 0; ni < 8; ni++)
#pragma unroll
                for (int r = 0; r < 4; r++) acc[ni][r] = 0.f;

#pragma unroll
            for (int s = 0; s < 4; s++) {
                unsigned bf[8][2];
#pragma unroll
                for (int i = 0; i < 4; i++) {
                    unsigned addr = ks_base +
                        (unsigned)(((rowoff + (2 * i + ni_off) * 8 + mrr) * QSTR
                                    + 16 * s + kh_off) * 2);
                    ldsm_x4(bf[2 * i][0], bf[2 * i][1], bf[2 * i + 1][0], bf[2 * i + 1][1], addr);
                }
#pragma unroll
                for (int ni = 0; ni < 8; ni++) mma16(acc[ni], qf[s], bf[ni]);
            }

            unsigned pf[4][4];
#pragma unroll
            for (int ni = 0; ni < 8; ni++) {
                int c = ni * 8 + 2 * tig;
                int kg = k0 + c;
                float2 mv0 = *(const float2*)&mrow0[kg];
                float2 mv1 = *(const float2*)&mrow1[kg];
                float p00 = ex2(acc[ni][0] + mv0.x - z0);
                float p01 = ex2(acc[ni][1] + mv0.y - z0);
                float p10 = ex2(acc[ni][2] + mv1.x - z1);
                float p11 = ex2(acc[ni][3] + mv1.y - z1);
                *(float2*)&attnb[(size_t)(q0 + r0) * SEQ + kg] = make_float2(p00, p01);
                *(float2*)&attnb[(size_t)(q0 + r1) * SEQ + kg] = make_float2(p10, p11);
                int sp = ni >> 1;
                if (ni & 1) { pf[sp][2] = pack2(p00, p01); pf[sp][3] = pack2(p10, p11); }
                else        { pf[sp][0] = pack2(p00, p01); pf[sp][1] = pack2(p10, p11); }
            }

#pragma unroll
            for (int s = 0; s < 4; s++) {
                unsigned vbf[8][2];
#pragma unroll
                for (int i = 0; i < 4; i++) {
                    unsigned addr = vs_base +
                        (unsigned)(((rowoff + 16 * s + kh_off + mrr) * QSTR
                                    + (2 * i + ni_off) * 8) * 2);
                    ldsm_x4_t(vbf[2 * i][0], vbf[2 * i][1], vbf[2 * i + 1][0], vbf[2 * i + 1][1], addr);
                }
#pragma unroll
                for (int ni = 0; ni < 8; ni++) mma16(cacc[ni], pf[s], vbf[ni]);
            }
        }
        __syncthreads();
        buf ^= 1;
    }

    const int b = bh >> 4;
    const int hh = bh & 15;
#pragma unroll
    for (int ni = 0; ni < 8; ni++) {
        int d0 = ni * 8 + 2 * tig;
        *(unsigned*)&ctx[((size_t)b * SEQ + q0 + r0) * D_MODEL + hh * DEPTH + d0] =
            pack2(cacc[ni][0], cacc[ni][1]);
        *(unsigned*)&ctx[((size_t)b * SEQ + q0 + r1) * D_MODEL + hh * DEPTH + d0] =
            pack2(cacc[ni][2], cacc[ni][3]);
    }
}

// ---------------------------------------------------------------------------
// Inputs: v, k, q, mask, wq_w, wq_b, wk_w, wk_b, wv_w, wv_b, dense_w, dense_b
// Output: [out (B*S*D_MODEL) | attn (B*H*S*S)] fp32
// ---------------------------------------------------------------------------
extern "C" void kernel_launch(void* const* d_in, const int* in_sizes, int n_in,
                              void* d_out, int out_size)
{
    const float* v_in = (const float*)d_in[0];
    const float* k_in = (const float*)d_in[1];
    const float* q_in = (const float*)d_in[2];
    const float* mask = (const float*)d_in[3];
    const float* wq_w = (const float*)d_in[4];
    const float* wq_b = (const float*)d_in[5];
    const float* wk_w = (const float*)d_in[6];
    const float* wk_b = (const float*)d_in[7];
    const float* wv_w = (const float*)d_in[8];
    const float* wv_b = (const float*)d_in[9];
    const float* dw   = (const float*)d_in[10];
    const float* db   = (const float*)d_in[11];

    float* out  = (float*)d_out;
    float* attn = out + (size_t)BATCH * SEQ * D_MODEL;

    __half *gq, *gk, *gv, *gctx, *gxh, *gwh;
    float* gmt;
    cudaGetSymbolAddress((void**)&gq,   g_Q);
    cudaGetSymbolAddress((void**)&gk,   g_K);
    cudaGetSymbolAddress((void**)&gv,   g_V);
    cudaGetSymbolAddress((void**)&gctx, g_CTX);
    cudaGetSymbolAddress((void**)&gxh,  g_XH);
    cudaGetSymbolAddress((void**)&gwh,  g_WH);
    cudaGetSymbolAddress((void**)&gmt,  g_MT);

    const size_t XN = (size_t)MTOT * D_MODEL;
    const size_t WN = (size_t)D_MODEL * D_MODEL;
    __half* xh_v = gxh;
    __half* xh_k = gxh + XN;
    __half* xh_q = gxh + 2 * XN;
    __half* wh_q = gwh;
    __half* wh_k = gwh + WN;
    __half* wh_v = gwh + 2 * WN;
    __half* wh_d = gwh + 3 * WN;

    ConvJobs jobs;
    jobs.src[0] = v_in;  jobs.dst[0] = xh_v; jobs.n[0] = (int)XN;
    jobs.src[1] = k_in;  jobs.dst[1] = xh_k; jobs.n[1] = (int)XN;
    jobs.src[2] = q_in;  jobs.dst[2] = xh_q; jobs.n[2] = (int)XN;
    jobs.src[3] = wq_w;  jobs.dst[3] = wh_q; jobs.n[3] = (int)WN;
    jobs.src[4] = wk_w;  jobs.dst[4] = wh_k; jobs.n[4] = (int)WN;
    jobs.src[5] = wv_w;  jobs.dst[5] = wh_v; jobs.n[5] = (int)WN;
    jobs.src[6] = dw;    jobs.dst[6] = wh_d; jobs.n[6] = (int)WN;

    dim3 gcv(1024, 1, 7);
    convert_f2h<<<gcv, 256>>>(jobs);
    scale_mask<<<1024, 256>>>(mask, gmt, SEQ * SEQ);

    const int gsmem = 3 * 2 * 128 * GSTR * (int)sizeof(__half);   // 61440
    cudaFuncSetAttribute(gemm_f16<1, __half>,
                         cudaFuncAttributeMaxDynamicSharedMemorySize, gsmem);
    cudaFuncSetAttribute(gemm_f16<0, float>,
                         cudaFuncAttributeMaxDynamicSharedMemorySize, gsmem);

    dim3 gp(D_MODEL / 128, MTOT / 128);
    gemm_f16<1, __half><<<gp, 256, gsmem>>>(xh_q, wh_q, wq_b, gq, MTOT, D_MODEL, D_MODEL, QSCALE);
    gemm_f16<1, __half><<<gp, 256, gsmem>>>(xh_k, wh_k, wk_b, gk, MTOT, D_MODEL, D_MODEL, 1.0f);
    gemm_f16<1, __half><<<gp, 256, gsmem>>>(xh_v, wh_v, wv_b, gv, MTOT, D_MODEL, D_MODEL, 1.0f);

    const int fsmem = 2 * 2 * KBB * QSTR * (int)sizeof(__half);   // 73728
    cudaFuncSetAttribute(fused_attn, cudaFuncAttributeMaxDynamicSharedMemorySize, fsmem);
    dim3 gf(SEQ / BQ, BHN);
    fused_attn<<<gf, 256, fsmem>>>(gq, gk, gv, gmt, attn, gctx);

    gemm_f16<0, float><<<gp, 256, gsmem>>>(gctx, wh_d, db, out, MTOT, D_MODEL, D_MODEL, 1.0f);
}

// round 15
// speedup vs baseline: 1.2427x; 1.2427x over previous
#include <cuda_runtime.h>
#include <cuda_fp16.h>
#include <cstddef>

#define D_MODEL 1024
#define NUM_HEADS 16
#define DEPTH 64
#define BATCH 4
#define SEQ 2048
#define BHN (BATCH * NUM_HEADS)
#define BQ 128
#define KBB 128
#define NKB (SEQ / KBB)         // 16
#define QSTR 72
#define GK 64                   // gemm K per stage
#define GSTR2 72                // gemm smem half stride (64 + 8 pad)
#define PSTR 68                 // P-stage float stride (64 + 4 pad)
#define MTOT (BATCH * SEQ)      // 8192
#define QSCALE 0.18033688011112042f     // 0.125 * log2(e)
#define MSCALE (-1.4426950408889634e9f) // -1e9 * log2(e)

// Scratch (device globals; no allocation allowed)
__device__ __half g_Q[(size_t)BHN * SEQ * DEPTH];
__device__ __half g_K[(size_t)BHN * SEQ * DEPTH];
__device__ __half g_V[(size_t)BHN * SEQ * DEPTH];
__device__ __half g_CTX[(size_t)BATCH * SEQ * D_MODEL];
__device__ __half g_XH[3][(size_t)MTOT * D_MODEL];
__device__ __half g_WH[4][(size_t)D_MODEL * D_MODEL];
__device__ float  g_MT[(size_t)SEQ * SEQ];   // mask * (-1e9*log2e)
__device__ int    g_NZ;                      // mask has any nonzero?

// ---------------------------------------------------------------------------
// Helpers
// ---------------------------------------------------------------------------
__device__ __forceinline__ unsigned pack2(float a, float b) {
    __half2 h = __floats2half2_rn(a, b);
    return *(unsigned*)&h;
}
__device__ __forceinline__ float ex2(float x) {
    float r; asm("ex2.approx.ftz.f32 %0, %1;" : "=f"(r) : "f"(x)); return r;
}
__device__ __forceinline__ float lg2(float x) {
    float r; asm("lg2.approx.f32 %0, %1;" : "=f"(r) : "f"(x)); return r;
}

__device__ __forceinline__ void mma16(float* d, const unsigned* a, const unsigned* b) {
    asm volatile(
        "mma.sync.aligned.m16n8k16.row.col.f32.f16.f16.f32 "
        "{%0,%1,%2,%3}, {%4,%5,%6,%7}, {%8,%9}, {%0,%1,%2,%3};\n"
        : "+f"(d[0]), "+f"(d[1]), "+f"(d[2]), "+f"(d[3])
        : "r"(a[0]), "r"(a[1]), "r"(a[2]), "r"(a[3]), "r"(b[0]), "r"(b[1]));
}

__device__ __forceinline__ void ldsm_x4(unsigned& r0, unsigned& r1,
                                        unsigned& r2, unsigned& r3, unsigned addr) {
    asm volatile("ldmatrix.sync.aligned.m8n8.x4.shared.b16 {%0,%1,%2,%3}, [%4];"
                 : "=r"(r0), "=r"(r1), "=r"(r2), "=r"(r3) : "r"(addr));
}
__device__ __forceinline__ void ldsm_x4_t(unsigned& r0, unsigned& r1,
                                          unsigned& r2, unsigned& r3, unsigned addr) {
    asm volatile("ldmatrix.sync.aligned.m8n8.x4.trans.shared.b16 {%0,%1,%2,%3}, [%4];"
                 : "=r"(r0), "=r"(r1), "=r"(r2), "=r"(r3) : "r"(addr));
}

__device__ __forceinline__ void cp16(unsigned smem_addr, const void* gptr) {
    asm volatile("cp.async.cg.shared.global [%0], [%1], 16;"
                 :: "r"(smem_addr), "l"(gptr));
}
__device__ __forceinline__ void cp_commit() { asm volatile("cp.async.commit_group;"); }
__device__ __forceinline__ void cp_wait0()  { asm volatile("cp.async.wait_group 0;"); }

// ---------------------------------------------------------------------------
// Convert fp32 -> half (inputs + weights); mask -> scaled fp32 + nonzero flag.
// ---------------------------------------------------------------------------
struct ConvJobs {
    const float* src[7];
    __half* dst[7];
    int n[7];
};

__global__ void __launch_bounds__(256)
convert_f2h(ConvJobs jobs)
{
    const int z = blockIdx.z;
    const float* s = jobs.src[z];
    __half* d = jobs.dst[z];
    const int n = jobs.n[z];
    for (int i = (blockIdx.x * 256 + threadIdx.x) * 4; i < n; i += gridDim.x * 256 * 4) {
        float4 v = *(const float4*)(s + i);
        *(uint2*)(d + i) = make_uint2(pack2(v.x, v.y), pack2(v.z, v.w));
    }
}

__global__ void zero_nz() { g_NZ = 0; }

__global__ void __launch_bounds__(256)
scale_mask(const float* __restrict__ mask, float* __restrict__ mt, int n)
{
    int nz = 0;
    for (int i = (blockIdx.x * 256 + threadIdx.x) * 4; i < n; i += gridDim.x * 256 * 4) {
        float4 v = *(const float4*)(mask + i);
        nz |= (v.x != 0.f) | (v.y != 0.f) | (v.z != 0.f) | (v.w != 0.f);
        v.x *= MSCALE; v.y *= MSCALE; v.z *= MSCALE; v.w *= MSCALE;
        *(float4*)(mt + i) = v;
    }
    if (__syncthreads_or(nz) && threadIdx.x == 0) atomicExch(&g_NZ, 1);
}

// ---------------------------------------------------------------------------
// GEMM: C = (A(MxK) @ W(NxK)^T + bias) * oscale
// half operands, fp32 accum, ldmatrix frags, BK=64, 2-stage cp.async.
// ---------------------------------------------------------------------------
template <int HEADMAJOR, typename TO>
__global__ void __launch_bounds__(256, 2)
gemm_f16(const __half* __restrict__ A, const __half* __restrict__ W,
         const float* __restrict__ bias, TO* __restrict__ C,
         int M, int N, int K, float oscale)
{
    const int BM = 128, BN = 128;
    extern __shared__ __half gsm[];
    const unsigned stage_bytes = BM * GSTR2 * 2;        // 18432
    const unsigned as_base = (unsigned)__cvta_generic_to_shared(gsm);
    const unsigned bs_base = as_base + 2 * stage_bytes;

    const int m0 = blockIdx.y * BM;
    const int n0 = blockIdx.x * BN;
    const int t = threadIdx.x;
    const int warp = t >> 5, lane = t & 31;
    const int wm = (warp >> 2) * 64, wn = (warp & 3) * 32;
    const int gid = lane >> 2, tig = lane & 3;

    const int mtx = lane >> 3;
    const int mrr = lane & 7;
    const int a_roff = (mtx & 1) * 8;
    const int a_koff = (mtx >> 1) * 8;
    const int ni_off = mtx >> 1;
    const int kh_off = (mtx & 1) * 8;

    // staging: 128 rows x 64 halves; 2 threads/row, sc in {0,32}
    const int sr = t >> 1;
    const int sc = (t & 1) << 5;

    auto stage = [&](int kt, int b) {
        const __half* Ab = A + (size_t)(m0 + sr) * K + kt * GK + sc;
        const __half* Wb = W + (size_t)(n0 + sr) * K + kt * GK + sc;
        unsigned ao = as_base + b * stage_bytes + (unsigned)((sr * GSTR2 + sc) * 2);
        unsigned bo = bs_base + b * stage_bytes + (unsigned)((sr * GSTR2 + sc) * 2);
        cp16(ao,      Ab);      cp16(ao + 16, Ab + 8);
        cp16(ao + 32, Ab + 16); cp16(ao + 48, Ab + 24);
        cp16(bo,      Wb);      cp16(bo + 16, Wb + 8);
        cp16(bo + 32, Wb + 16); cp16(bo + 48, Wb + 24);
    };

    float acc[4][4][4];
#pragma unroll
    for (int mi = 0; mi < 4; mi++)
#pragma unroll
        for (int ni = 0; ni < 4; ni++)
#pragma unroll
            for (int r = 0; r < 4; r++) acc[mi][ni][r] = 0.f;

    const int NKT = K / GK;   // 16
    stage(0, 0); cp_commit();

    int buf = 0;
    for (int kt = 0; kt < NKT; kt++) {
        cp_wait0();
        __syncthreads();
        if (kt + 1 < NKT) { stage(kt + 1, buf ^ 1); cp_commit(); }

#pragma unroll
        for (int ks = 0; ks < GK; ks += 16) {
            unsigned af[4][4], bf[4][2];
#pragma unroll
            for (int mi = 0; mi < 4; mi++) {
                unsigned addr = as_base + buf * stage_bytes +
                    (unsigned)(((wm + mi * 16 + a_roff + mrr) * GSTR2 + ks + a_koff) * 2);
                ldsm_x4(af[mi][0], af[mi][1], af[mi][2], af[mi][3], addr);
            }
#pragma unroll
            for (int i = 0; i < 2; i++) {
                unsigned addr = bs_base + buf * stage_bytes +
                    (unsigned)(((wn + (2 * i + ni_off) * 8 + mrr) * GSTR2 + ks + kh_off) * 2);
                ldsm_x4(bf[2 * i][0], bf[2 * i][1], bf[2 * i + 1][0], bf[2 * i + 1][1], addr);
            }
#pragma unroll
            for (int mi = 0; mi < 4; mi++)
#pragma unroll
                for (int ni = 0; ni < 4; ni++)
                    mma16(acc[mi][ni], af[mi], bf[ni]);
        }
        __syncthreads();
        buf ^= 1;
    }

#pragma unroll
    for (int mi = 0; mi < 4; mi++) {
        int r0 = m0 + wm + mi * 16 + gid;
#pragma unroll
        for (int ni = 0; ni < 4; ni++) {
            int c0 = n0 + wn + ni * 8 + 2 * tig;
            float b0 = bias[c0], b1 = bias[c0 + 1];
            float v0 = (acc[mi][ni][0] + b0) * oscale;
            float v1 = (acc[mi][ni][1] + b1) * oscale;
            float v2 = (acc[mi][ni][2] + b0) * oscale;
            float v3 = (acc[mi][ni][3] + b1) * oscale;
            if constexpr (HEADMAJOR) {
                int h = c0 >> 6, d = c0 & (DEPTH - 1);
                {
                    int m = r0, bb = m >> 11, s = m & (SEQ - 1);
                    __half* dst = (__half*)C +
                        (((size_t)(bb * NUM_HEADS + h)) * SEQ + s) * DEPTH + d;
                    *(unsigned*)dst = pack2(v0, v1);
                }
                {
                    int m = r0 + 8, bb = m >> 11, s = m & (SEQ - 1);
                    __half* dst = (__half*)C +
                        (((size_t)(bb * NUM_HEADS + h)) * SEQ + s) * DEPTH + d;
                    *(unsigned*)dst = pack2(v2, v3);
                }
            } else {
                float* dst = (float*)C;
                *(float2*)&dst[(size_t)r0 * N + c0]       = make_float2(v0, v1);
                *(float2*)&dst[(size_t)(r0 + 8) * N + c0] = make_float2(v2, v3);
            }
        }
    }
}

// ---------------------------------------------------------------------------
// Fused attention. Base-2 softmax (Q pre-scaled). Mask-zero runtime fast
// path. Pass B stages normalized P in padded smem and streams coalesced
// float4 stores to attn.
// Dynamic smem: K[2][128][QSTR] + V[2][128][QSTR] halves + P[128][PSTR] float
// ---------------------------------------------------------------------------
__global__ void __launch_bounds__(256, 2)
fused_attn(const __half* __restrict__ Q, const __half* __restrict__ Kmat,
           const __half* __restrict__ V, const float* __restrict__ mt,
           const int* __restrict__ nzp,
           float* __restrict__ attn, __half* __restrict__ ctx)
{
    extern __shared__ __half dsm[];
    const unsigned ks_base = (unsigned)__cvta_generic_to_shared(dsm);
    const unsigned vs_base = ks_base + 2 * KBB * QSTR * 2;
    const unsigned buf_stride = KBB * QSTR * 2;
    float* psm = (float*)(dsm + 4 * KBB * QSTR);   // P stage: 128 x PSTR floats

    const int bh = blockIdx.y;
    const int q0 = blockIdx.x * BQ;
    const __half* Qb = Q    + (size_t)bh * SEQ * DEPTH;
    const __half* Kb = Kmat + (size_t)bh * SEQ * DEPTH;
    const __half* Vb = V    + (size_t)bh * SEQ * DEPTH;
    float* attnb = attn + (size_t)bh * SEQ * SEQ;

    const int t = threadIdx.x;
    const int warp = t >> 5, lane = t & 31;
    const int gid = lane >> 2, tig = lane & 3;
    const int r0 = warp * 16 + gid;
    const int r1 = r0 + 8;

    const int mtx = lane >> 3;
    const int mrr = lane & 7;
    const int ni_off = mtx >> 1;
    const int kh_off = (mtx & 1) * 8;

    const int sr = t >> 1;
    const int sc = (t & 1) << 5;

    const bool hasmask = (*nzp) != 0;

    auto stageK = [&](int kb, int b) {
        const __half* g = Kb + (size_t)(kb * KBB + sr) * DEPTH + sc;
        unsigned o = ks_base + b * buf_stride + (unsigned)((sr * QSTR + sc) * 2);
        cp16(o, g); cp16(o + 16, g + 8);
        cp16(o + 32, g + 16); cp16(o + 48, g + 24);
    };
    auto stageV = [&](int kb, int b) {
        const __half* g = Vb + (size_t)(kb * KBB + sr) * DEPTH + sc;
        unsigned o = vs_base + b * buf_stride + (unsigned)((sr * QSTR + sc) * 2);
        cp16(o, g); cp16(o + 16, g + 8);
        cp16(o + 32, g + 16); cp16(o + 48, g + 24);
    };

    // Q fragments in registers (Q pre-scaled by 0.125*log2e)
    unsigned qf[4][4];
#pragma unroll
    for (int s = 0; s < 4; s++) {
        qf[s][0] = *(const unsigned*)&Qb[(size_t)(q0 + r0) * DEPTH + 16 * s + 2 * tig];
        qf[s][1] = *(const unsigned*)&Qb[(size_t)(q0 + r1) * DEPTH + 16 * s + 2 * tig];
        qf[s][2] = *(const unsigned*)&Qb[(size_t)(q0 + r0) * DEPTH + 16 * s + 8 + 2 * tig];
        qf[s][3] = *(const unsigned*)&Qb[(size_t)(q0 + r1) * DEPTH + 16 * s + 8 + 2 * tig];
    }

    const float* mrow0 = mt + (size_t)(q0 + r0) * SEQ;
    const float* mrow1 = mt + (size_t)(q0 + r1) * SEQ;

    float m0 = -1e30f, m1 = -1e30f, l0 = 0.f, l1 = 0.f;

    // ------------------------- Pass A: stats -------------------------
    stageK(0, 0);
    cp_commit();
    int buf = 0;
    for (int kb = 0; kb < NKB; kb++) {
        cp_wait0();
        __syncthreads();
        if (kb + 1 < NKB) { stageK(kb + 1, buf ^ 1); cp_commit(); }

#pragma unroll
        for (int ch = 0; ch < 2; ch++) {
            const int k0 = kb * KBB + ch * 64;
            const int rowoff = buf * KBB + ch * 64;

            float acc[8][4];
#pragma unroll
            for (int ni = 0; ni < 8; ni++)
#pragma unroll
                for (int r = 0; r < 4; r++) acc[ni][r] = 0.f;

#pragma unroll
            for (int s = 0; s < 4; s++) {
                unsigned bf[8][2];
#pragma unroll
                for (int i = 0; i < 4; i++) {
                    unsigned addr = ks_base +
                        (unsigned)(((rowoff + (2 * i + ni_off) * 8 + mrr) * QSTR
                                    + 16 * s + kh_off) * 2);
                    ldsm_x4(bf[2 * i][0], bf[2 * i][1], bf[2 * i + 1][0], bf[2 * i + 1][1], addr);
                }
#pragma unroll
                for (int ni = 0; ni < 8; ni++) mma16(acc[ni], qf[s], bf[ni]);
            }

            if (hasmask) {
#pragma unroll
                for (int ni = 0; ni < 8; ni++) {
                    int c = ni * 8 + 2 * tig;
                    float2 mv0 = *(const float2*)&mrow0[k0 + c];
                    float2 mv1 = *(const float2*)&mrow1[k0 + c];
                    acc[ni][0] += mv0.x; acc[ni][1] += mv0.y;
                    acc[ni][2] += mv1.x; acc[ni][3] += mv1.y;
                }
            }

            float rm0 = -1e30f, rm1 = -1e30f;
#pragma unroll
            for (int ni = 0; ni < 8; ni++) {
                rm0 = fmaxf(rm0, fmaxf(acc[ni][0], acc[ni][1]));
                rm1 = fmaxf(rm1, fmaxf(acc[ni][2], acc[ni][3]));
            }
            rm0 = fmaxf(rm0, __shfl_xor_sync(0xffffffffu, rm0, 1));
            rm0 = fmaxf(rm0, __shfl_xor_sync(0xffffffffu, rm0, 2));
            rm1 = fmaxf(rm1, __shfl_xor_sync(0xffffffffu, rm1, 1));
            rm1 = fmaxf(rm1, __shfl_xor_sync(0xffffffffu, rm1, 2));

            float mn0 = fmaxf(m0, rm0), mn1 = fmaxf(m1, rm1);
            float sc0 = ex2(m0 - mn0), sc1 = ex2(m1 - mn1);
            m0 = mn0; m1 = mn1;

            float ts0 = 0.f, ts1 = 0.f;
#pragma unroll
            for (int ni = 0; ni < 8; ni++) {
                ts0 += ex2(acc[ni][0] - m0) + ex2(acc[ni][1] - m0);
                ts1 += ex2(acc[ni][2] - m1) + ex2(acc[ni][3] - m1);
            }
            ts0 += __shfl_xor_sync(0xffffffffu, ts0, 1);
            ts0 += __shfl_xor_sync(0xffffffffu, ts0, 2);
            ts1 += __shfl_xor_sync(0xffffffffu, ts1, 1);
            ts1 += __shfl_xor_sync(0xffffffffu, ts1, 2);

            l0 = l0 * sc0 + ts0;
            l1 = l1 * sc1 + ts1;
        }
        __syncthreads();
        buf ^= 1;
    }

    const float z0 = m0 + lg2(l0);
    const float z1 = m1 + lg2(l1);

    // ------------------------- Pass B: write + PV -------------------------
    float cacc[8][4];
#pragma unroll
    for (int ni = 0; ni < 8; ni++)
#pragma unroll
        for (int r = 0; r < 4; r++) cacc[ni][r] = 0.f;

    stageK(0, 0); stageV(0, 0);
    cp_commit();
    buf = 0;
    for (int kb = 0; kb < NKB; kb++) {
        cp_wait0();
        __syncthreads();
        if (kb + 1 < NKB) { stageK(kb + 1, buf ^ 1); stageV(kb + 1, buf ^ 1); cp_commit(); }

#pragma unroll
        for (int ch = 0; ch < 2; ch++) {
            const int k0 = kb * KBB + ch * 64;
            const int rowoff = buf * KBB + ch * 64;

            float acc[8][4];
#pragma unroll
            for (int ni = 0; ni < 8; ni++)
#pragma unroll
                for (int r = 0; r < 4; r++) acc[ni][r] = 0.f;

#pragma unroll
            for (int s = 0; s < 4; s++) {
                unsigned bf[8][2];
#pragma unroll
                for (int i = 0; i < 4; i++) {
                    unsigned addr = ks_base +
                        (unsigned)(((rowoff + (2 * i + ni_off) * 8 + mrr) * QSTR
                                    + 16 * s + kh_off) * 2);
                    ldsm_x4(bf[2 * i][0], bf[2 * i][1], bf[2 * i + 1][0], bf[2 * i + 1][1], addr);
                }
#pragma unroll
                for (int ni = 0; ni < 8; ni++) mma16(acc[ni], qf[s], bf[ni]);
            }

            if (hasmask) {
#pragma unroll
                for (int ni = 0; ni < 8; ni++) {
                    int c = ni * 8 + 2 * tig;
                    float2 mv0 = *(const float2*)&mrow0[k0 + c];
                    float2 mv1 = *(const float2*)&mrow1[k0 + c];
                    acc[ni][0] += mv0.x; acc[ni][1] += mv0.y;
                    acc[ni][2] += mv1.x; acc[ni][3] += mv1.y;
                }
            }

            // p = ex2(s2 - z) ; stage to psm ; pack PV A-frags
            unsigned pf[4][4];
#pragma unroll
            for (int ni = 0; ni < 8; ni++) {
                int c = ni * 8 + 2 * tig;
                float p00 = ex2(acc[ni][0] - z0);
                float p01 = ex2(acc[ni][1] - z0);
                float p10 = ex2(acc[ni][2] - z1);
                float p11 = ex2(acc[ni][3] - z1);
                *(float2*)&psm[r0 * PSTR + c] = make_float2(p00, p01);
                *(float2*)&psm[r1 * PSTR + c] = make_float2(p10, p11);
                int sp = ni >> 1;
                if (ni & 1) { pf[sp][2] = pack2(p00, p01); pf[sp][3] = pack2(p10, p11); }
                else        { pf[sp][0] = pack2(p00, p01); pf[sp][1] = pack2(p10, p11); }
            }

            // ctx += P @ V (registers; independent of psm)
#pragma unroll
            for (int s = 0; s < 4; s++) {
                unsigned vbf[8][2];
#pragma unroll
                for (int i = 0; i < 4; i++) {
                    unsigned addr = vs_base +
                        (unsigned)(((rowoff + 16 * s + kh_off + mrr) * QSTR
                                    + (2 * i + ni_off) * 8) * 2);
                    ldsm_x4_t(vbf[2 * i][0], vbf[2 * i][1], vbf[2 * i + 1][0], vbf[2 * i + 1][1], addr);
                }
#pragma unroll
                for (int ni = 0; ni < 8; ni++) mma16(cacc[ni], pf[s], vbf[ni]);
            }

            // coalesced attn store of the staged P tile
            __syncthreads();
#pragma unroll
            for (int i = 0; i < 8; i++) {
                int idx = t + i * 256;
                int row = idx >> 4;
                int c4 = (idx & 15) << 2;
                float4 v = *(const float4*)&psm[row * PSTR + c4];
                *(float4*)&attnb[(size_t)(q0 + row) * SEQ + k0 + c4] = v;
            }
            __syncthreads();
        }
        buf ^= 1;
    }

    const int b = bh >> 4;
    const int hh = bh & 15;
#pragma unroll
    for (int ni = 0; ni < 8; ni++) {
        int d0 = ni * 8 + 2 * tig;
        *(unsigned*)&ctx[((size_t)b * SEQ + q0 + r0) * D_MODEL + hh * DEPTH + d0] =
            pack2(cacc[ni][0], cacc[ni][1]);
        *(unsigned*)&ctx[((size_t)b * SEQ + q0 + r1) * D_MODEL + hh * DEPTH + d0] =
            pack2(cacc[ni][2], cacc[ni][3]);
    }
}

// ---------------------------------------------------------------------------
// Inputs: v, k, q, mask, wq_w, wq_b, wk_w, wk_b, wv_w, wv_b, dense_w, dense_b
// Output: [out (B*S*D_MODEL) | attn (B*H*S*S)] fp32
// ---------------------------------------------------------------------------
extern "C" void kernel_launch(void* const* d_in, const int* in_sizes, int n_in,
                              void* d_out, int out_size)
{
    const float* v_in = (const float*)d_in[0];
    const float* k_in = (const float*)d_in[1];
    const float* q_in = (const float*)d_in[2];
    const float* mask = (const float*)d_in[3];
    const float* wq_w = (const float*)d_in[4];
    const float* wq_b = (const float*)d_in[5];
    const float* wk_w = (const float*)d_in[6];
    const float* wk_b = (const float*)d_in[7];
    const float* wv_w = (const float*)d_in[8];
    const float* wv_b = (const float*)d_in[9];
    const float* dw   = (const float*)d_in[10];
    const float* db   = (const float*)d_in[11];

    float* out  = (float*)d_out;
    float* attn = out + (size_t)BATCH * SEQ * D_MODEL;

    __half *gq, *gk, *gv, *gctx, *gxh, *gwh;
    float* gmt;
    int* gnz;
    cudaGetSymbolAddress((void**)&gq,   g_Q);
    cudaGetSymbolAddress((void**)&gk,   g_K);
    cudaGetSymbolAddress((void**)&gv,   g_V);
    cudaGetSymbolAddress((void**)&gctx, g_CTX);
    cudaGetSymbolAddress((void**)&gxh,  g_XH);
    cudaGetSymbolAddress((void**)&gwh,  g_WH);
    cudaGetSymbolAddress((void**)&gmt,  g_MT);
    cudaGetSymbolAddress((void**)&gnz,  g_NZ);

    const size_t XN = (size_t)MTOT * D_MODEL;
    const size_t WN = (size_t)D_MODEL * D_MODEL;
    __half* xh_v = gxh;
    __half* xh_k = gxh + XN;
    __half* xh_q = gxh + 2 * XN;
    __half* wh_q = gwh;
    __half* wh_k = gwh + WN;
    __half* wh_v = gwh + 2 * WN;
    __half* wh_d = gwh + 3 * WN;

    ConvJobs jobs;
    jobs.src[0] = v_in;  jobs.dst[0] = xh_v; jobs.n[0] = (int)XN;
    jobs.src[1] = k_in;  jobs.dst[1] = xh_k; jobs.n[1] = (int)XN;
    jobs.src[2] = q_in;  jobs.dst[2] = xh_q; jobs.n[2] = (int)XN;
    jobs.src[3] = wq_w;  jobs.dst[3] = wh_q; jobs.n[3] = (int)WN;
    jobs.src[4] = wk_w;  jobs.dst[4] = wh_k; jobs.n[4] = (int)WN;
    jobs.src[5] = wv_w;  jobs.dst[5] = wh_v; jobs.n[5] = (int)WN;
    jobs.src[6] = dw;    jobs.dst[6] = wh_d; jobs.n[6] = (int)WN;

    zero_nz<<<1, 1>>>();
    dim3 gcv(1024, 1, 7);
    convert_f2h<<<gcv, 256>>>(jobs);
    scale_mask<<<1024, 256>>>(mask, gmt, SEQ * SEQ);

    const int gsmem = 2 * 2 * 128 * GSTR2 * (int)sizeof(__half);   // 73728
    cudaFuncSetAttribute(gemm_f16<1, __half>,
                         cudaFuncAttributeMaxDynamicSharedMemorySize, gsmem);
    cudaFuncSetAttribute(gemm_f16<0, float>,
                         cudaFuncAttributeMaxDynamicSharedMemorySize, gsmem);

    dim3 gp(D_MODEL / 128, MTOT / 128);
    gemm_f16<1, __half><<<gp, 256, gsmem>>>(xh_q, wh_q, wq_b, gq, MTOT, D_MODEL, D_MODEL, QSCALE);
    gemm_f16<1, __half><<<gp, 256, gsmem>>>(xh_k, wh_k, wk_b, gk, MTOT, D_MODEL, D_MODEL, 1.0f);
    gemm_f16<1, __half><<<gp, 256, gsmem>>>(xh_v, wh_v, wv_b, gv, MTOT, D_MODEL, D_MODEL, 1.0f);

    const int fsmem = 4 * KBB * QSTR * (int)sizeof(__half)          // K+V double buf
                    + 128 * PSTR * (int)sizeof(float);              // P stage
    cudaFuncSetAttribute(fused_attn, cudaFuncAttributeMaxDynamicSharedMemorySize, fsmem);
    dim3 gf(SEQ / BQ, BHN);
    fused_attn<<<gf, 256, fsmem>>>(gq, gk, gv, gmt, gnz, attn, gctx);

    gemm_f16<0, float><<<gp, 256, gsmem>>>(gctx, wh_d, db, out, MTOT, D_MODEL, D_MODEL, 1.0f);
}

// round 17
// speedup vs baseline: 1.3374x; 1.0763x over previous
#include <cuda_runtime.h>
#include <cuda_fp16.h>
#include <cstddef>

#define D_MODEL 1024
#define NUM_HEADS 16
#define DEPTH 64
#define BATCH 4
#define SEQ 2048
#define BHN (BATCH * NUM_HEADS)
#define BQ 128
#define KBB 128
#define NKB (SEQ / KBB)         // 16
#define QSTR 72
#define GSTR 40                 // gemm smem half stride (32 + 8 pad)
#define PSTR 68                 // P-stage float stride (64 + 4 pad)
#define MTOT (BATCH * SEQ)      // 8192
#define QSCALE 0.18033688011112042f     // 0.125 * log2(e)
#define MSCALE (-1.4426950408889634e9f) // -1e9 * log2(e)

// Scratch (device globals; no allocation allowed)
__device__ __half g_Q[(size_t)BHN * SEQ * DEPTH];
__device__ __half g_K[(size_t)BHN * SEQ * DEPTH];
__device__ __half g_V[(size_t)BHN * SEQ * DEPTH];
__device__ __half g_CTX[(size_t)BATCH * SEQ * D_MODEL];
__device__ __half g_XH[3][(size_t)MTOT * D_MODEL];
__device__ __half g_WH[4][(size_t)D_MODEL * D_MODEL];
__device__ float  g_MT[(size_t)SEQ * SEQ];   // mask * (-1e9*log2e)
__device__ int    g_NZ;                      // mask has any nonzero?

// ---------------------------------------------------------------------------
// Helpers
// ---------------------------------------------------------------------------
__device__ __forceinline__ unsigned pack2(float a, float b) {
    __half2 h = __floats2half2_rn(a, b);
    return *(unsigned*)&h;
}
__device__ __forceinline__ float ex2(float x) {
    float r; asm("ex2.approx.ftz.f32 %0, %1;" : "=f"(r) : "f"(x)); return r;
}
__device__ __forceinline__ float lg2(float x) {
    float r; asm("lg2.approx.f32 %0, %1;" : "=f"(r) : "f"(x)); return r;
}

__device__ __forceinline__ void mma16(float* d, const unsigned* a, const unsigned* b) {
    asm volatile(
        "mma.sync.aligned.m16n8k16.row.col.f32.f16.f16.f32 "
        "{%0,%1,%2,%3}, {%4,%5,%6,%7}, {%8,%9}, {%0,%1,%2,%3};\n"
        : "+f"(d[0]), "+f"(d[1]), "+f"(d[2]), "+f"(d[3])
        : "r"(a[0]), "r"(a[1]), "r"(a[2]), "r"(a[3]), "r"(b[0]), "r"(b[1]));
}

__device__ __forceinline__ void ldsm_x4(unsigned& r0, unsigned& r1,
                                        unsigned& r2, unsigned& r3, unsigned addr) {
    asm volatile("ldmatrix.sync.aligned.m8n8.x4.shared.b16 {%0,%1,%2,%3}, [%4];"
                 : "=r"(r0), "=r"(r1), "=r"(r2), "=r"(r3) : "r"(addr));
}
__device__ __forceinline__ void ldsm_x4_t(unsigned& r0, unsigned& r1,
                                          unsigned& r2, unsigned& r3, unsigned addr) {
    asm volatile("ldmatrix.sync.aligned.m8n8.x4.trans.shared.b16 {%0,%1,%2,%3}, [%4];"
                 : "=r"(r0), "=r"(r1), "=r"(r2), "=r"(r3) : "r"(addr));
}

__device__ __forceinline__ void cp16(unsigned smem_addr, const void* gptr) {
    asm volatile("cp.async.cg.shared.global [%0], [%1], 16;"
                 :: "r"(smem_addr), "l"(gptr));
}
__device__ __forceinline__ void cp_commit() { asm volatile("cp.async.commit_group;"); }
__device__ __forceinline__ void cp_wait0()  { asm volatile("cp.async.wait_group 0;"); }
__device__ __forceinline__ void cp_wait1()  { asm volatile("cp.async.wait_group 1;"); }

// ---------------------------------------------------------------------------
// Convert sweep: z=0..6 fp32->half; z=7 mask -> scaled fp32 + nz flag.
// ---------------------------------------------------------------------------
struct ConvJobs {
    const float* src[7];
    __half* dst[7];
    int n[7];
    const float* msrc;
    float* mdst;
    int mn;
};

__global__ void zero_nz() { g_NZ = 0; }

__global__ void __launch_bounds__(256)
convert_f2h(ConvJobs jobs)
{
    const int z = blockIdx.z;
    if (z < 7) {
        const float* s = jobs.src[z];
        __half* d = jobs.dst[z];
        const int n = jobs.n[z];
        for (int i = (blockIdx.x * 256 + threadIdx.x) * 4; i < n; i += gridDim.x * 256 * 4) {
            float4 v = *(const float4*)(s + i);
            *(uint2*)(d + i) = make_uint2(pack2(v.x, v.y), pack2(v.z, v.w));
        }
    } else {
        int nz = 0;
        for (int i = (blockIdx.x * 256 + threadIdx.x) * 4; i < jobs.mn;
             i += gridDim.x * 256 * 4) {
            float4 v = *(const float4*)(jobs.msrc + i);
            nz |= (v.x != 0.f) | (v.y != 0.f) | (v.z != 0.f) | (v.w != 0.f);
            v.x *= MSCALE; v.y *= MSCALE; v.z *= MSCALE; v.w *= MSCALE;
            *(float4*)(jobs.mdst + i) = v;
        }
        if (__syncthreads_or(nz) && threadIdx.x == 0) atomicExch(&g_NZ, 1);
    }
}

// ---------------------------------------------------------------------------
// Shared gemm mainloop body (3-stage cp.async, BK=32, ldmatrix frags).
// Computes acc for tile (m0, n0); caller handles the epilogue.
// ---------------------------------------------------------------------------
struct GemmCtx {
    unsigned as_base, bs_base;
    int wm, wn, gid, tig;
    int a_roff, a_koff, ni_off, kh_off, mrr;
    int sr, sc;
};

__device__ __forceinline__ void gemm_mainloop(
    const __half* __restrict__ A, const __half* __restrict__ W,
    int m0, int n0, int K, const GemmCtx& c, float acc[4][4][4])
{
    const unsigned stage_bytes = 128 * GSTR * 2;   // 10240
    const int BK = 32;

    auto stage = [&](int kt, int b) {
        const __half* Ab = A + (size_t)(m0 + c.sr) * K + kt * BK + c.sc;
        const __half* Wb = W + (size_t)(n0 + c.sr) * K + kt * BK + c.sc;
        unsigned ao = c.as_base + b * stage_bytes + (unsigned)((c.sr * GSTR + c.sc) * 2);
        unsigned bo = c.bs_base + b * stage_bytes + (unsigned)((c.sr * GSTR + c.sc) * 2);
        cp16(ao,      Ab);
        cp16(ao + 16, Ab + 8);
        cp16(bo,      Wb);
        cp16(bo + 16, Wb + 8);
    };

    const int NKT = K / BK;
    stage(0, 0); cp_commit();
    stage(1, 1); cp_commit();

    for (int kt = 0; kt < NKT; kt++) {
        if (kt < NKT - 1) cp_wait1(); else cp_wait0();
        __syncthreads();
        if (kt + 2 < NKT) { stage(kt + 2, (kt + 2) % 3); cp_commit(); }

        const int buf = kt % 3;
#pragma unroll
        for (int ks = 0; ks < BK; ks += 16) {
            unsigned af[4][4], bf[4][2];
#pragma unroll
            for (int mi = 0; mi < 4; mi++) {
                unsigned addr = c.as_base + buf * stage_bytes +
                    (unsigned)(((c.wm + mi * 16 + c.a_roff + c.mrr) * GSTR + ks + c.a_koff) * 2);
                ldsm_x4(af[mi][0], af[mi][1], af[mi][2], af[mi][3], addr);
            }
#pragma unroll
            for (int i = 0; i < 2; i++) {
                unsigned addr = c.bs_base + buf * stage_bytes +
                    (unsigned)(((c.wn + (2 * i + c.ni_off) * 8 + c.mrr) * GSTR + ks + c.kh_off) * 2);
                ldsm_x4(bf[2 * i][0], bf[2 * i][1], bf[2 * i + 1][0], bf[2 * i + 1][1], addr);
            }
#pragma unroll
            for (int mi = 0; mi < 4; mi++)
#pragma unroll
                for (int ni = 0; ni < 4; ni++)
                    mma16(acc[mi][ni], af[mi], bf[ni]);
        }
        __syncthreads();
    }
}

__device__ __forceinline__ GemmCtx make_ctx(unsigned smem_base)
{
    GemmCtx c;
    const int t = threadIdx.x;
    const int warp = t >> 5, lane = t & 31;
    c.wm = (warp >> 2) * 64; c.wn = (warp & 3) * 32;
    c.gid = lane >> 2; c.tig = lane & 3;
    const int mtx = lane >> 3;
    c.mrr = lane & 7;
    c.a_roff = (mtx & 1) * 8;
    c.a_koff = (mtx >> 1) * 8;
    c.ni_off = mtx >> 1;
    c.kh_off = (mtx & 1) * 8;
    c.sr = t >> 1;
    c.sc = (t & 1) << 4;
    c.as_base = smem_base;
    c.bs_base = smem_base + 3 * 128 * GSTR * 2;
    return c;
}

// ---------------------------------------------------------------------------
// Merged QKV projection gemm: grid.z in {0,1,2} selects job.
// Output scattered half (b,h,s,d).
// ---------------------------------------------------------------------------
struct ProjJobs {
    const __half* A[3];
    const __half* W[3];
    const float* bias[3];
    __half* C[3];
    float oscale[3];
};

__global__ void __launch_bounds__(256, 2)
gemm_qkv(ProjJobs jobs)
{
    extern __shared__ __half gsm[];
    const int z = blockIdx.z;
    const __half* A = jobs.A[z];
    const __half* W = jobs.W[z];
    const float* bias = jobs.bias[z];
    __half* C = jobs.C[z];
    const float oscale = jobs.oscale[z];

    const int m0 = blockIdx.y * 128;
    const int n0 = blockIdx.x * 128;
    GemmCtx c = make_ctx((unsigned)__cvta_generic_to_shared(gsm));

    float acc[4][4][4];
#pragma unroll
    for (int mi = 0; mi < 4; mi++)
#pragma unroll
        for (int ni = 0; ni < 4; ni++)
#pragma unroll
            for (int r = 0; r < 4; r++) acc[mi][ni][r] = 0.f;

    gemm_mainloop(A, W, m0, n0, D_MODEL, c, acc);

#pragma unroll
    for (int mi = 0; mi < 4; mi++) {
        int r0 = m0 + c.wm + mi * 16 + c.gid;
#pragma unroll
        for (int ni = 0; ni < 4; ni++) {
            int c0 = n0 + c.wn + ni * 8 + 2 * c.tig;
            float b0 = bias[c0], b1 = bias[c0 + 1];
            int h = c0 >> 6, d = c0 & (DEPTH - 1);
#pragma unroll
            for (int rr = 0; rr < 2; rr++) {
                int m = r0 + rr * 8;
                int bb = m >> 11, s = m & (SEQ - 1);
                __half* dst = C + (((size_t)(bb * NUM_HEADS + h)) * SEQ + s) * DEPTH + d;
                *(unsigned*)dst = pack2((acc[mi][ni][rr * 2] + b0) * oscale,
                                        (acc[mi][ni][rr * 2 + 1] + b1) * oscale);
            }
        }
    }
}

// ---------------------------------------------------------------------------
// Dense output gemm: fp32 row-major output.
// ---------------------------------------------------------------------------
__global__ void __launch_bounds__(256, 2)
gemm_dense(const __half* __restrict__ A, const __half* __restrict__ W,
           const float* __restrict__ bias, float* __restrict__ C)
{
    extern __shared__ __half gsm[];
    const int m0 = blockIdx.y * 128;
    const int n0 = blockIdx.x * 128;
    GemmCtx c = make_ctx((unsigned)__cvta_generic_to_shared(gsm));

    float acc[4][4][4];
#pragma unroll
    for (int mi = 0; mi < 4; mi++)
#pragma unroll
        for (int ni = 0; ni < 4; ni++)
#pragma unroll
            for (int r = 0; r < 4; r++) acc[mi][ni][r] = 0.f;

    gemm_mainloop(A, W, m0, n0, D_MODEL, c, acc);

#pragma unroll
    for (int mi = 0; mi < 4; mi++) {
        int r0 = m0 + c.wm + mi * 16 + c.gid;
#pragma unroll
        for (int ni = 0; ni < 4; ni++) {
            int c0 = n0 + c.wn + ni * 8 + 2 * c.tig;
            float b0 = bias[c0], b1 = bias[c0 + 1];
            *(float2*)&C[(size_t)r0 * D_MODEL + c0] =
                make_float2(acc[mi][ni][0] + b0, acc[mi][ni][1] + b1);
            *(float2*)&C[(size_t)(r0 + 8) * D_MODEL + c0] =
                make_float2(acc[mi][ni][2] + b0, acc[mi][ni][3] + b1);
        }
    }
}

// ---------------------------------------------------------------------------
// Fused attention (unchanged from R15): base-2 softmax, mask-zero fast path,
// coalesced attn stores via padded smem P stage.
// ---------------------------------------------------------------------------
__global__ void __launch_bounds__(256, 2)
fused_attn(const __half* __restrict__ Q, const __half* __restrict__ Kmat,
           const __half* __restrict__ V, const float* __restrict__ mt,
           const int* __restrict__ nzp,
           float* __restrict__ attn, __half* __restrict__ ctx)
{
    extern __shared__ __half dsm[];
    const unsigned ks_base = (unsigned)__cvta_generic_to_shared(dsm);
    const unsigned vs_base = ks_base + 2 * KBB * QSTR * 2;
    const unsigned buf_stride = KBB * QSTR * 2;
    float* psm = (float*)(dsm + 4 * KBB * QSTR);

    const int bh = blockIdx.y;
    const int q0 = blockIdx.x * BQ;
    const __half* Qb = Q    + (size_t)bh * SEQ * DEPTH;
    const __half* Kb = Kmat + (size_t)bh * SEQ * DEPTH;
    const __half* Vb = V    + (size_t)bh * SEQ * DEPTH;
    float* attnb = attn + (size_t)bh * SEQ * SEQ;

    const int t = threadIdx.x;
    const int warp = t >> 5, lane = t & 31;
    const int gid = lane >> 2, tig = lane & 3;
    const int r0 = warp * 16 + gid;
    const int r1 = r0 + 8;

    const int mtx = lane >> 3;
    const int mrr = lane & 7;
    const int ni_off = mtx >> 1;
    const int kh_off = (mtx & 1) * 8;

    const int sr = t >> 1;
    const int sc = (t & 1) << 5;

    const bool hasmask = (*nzp) != 0;

    auto stageK = [&](int kb, int b) {
        const __half* g = Kb + (size_t)(kb * KBB + sr) * DEPTH + sc;
        unsigned o = ks_base + b * buf_stride + (unsigned)((sr * QSTR + sc) * 2);
        cp16(o, g); cp16(o + 16, g + 8);
        cp16(o + 32, g + 16); cp16(o + 48, g + 24);
    };
    auto stageV = [&](int kb, int b) {
        const __half* g = Vb + (size_t)(kb * KBB + sr) * DEPTH + sc;
        unsigned o = vs_base + b * buf_stride + (unsigned)((sr * QSTR + sc) * 2);
        cp16(o, g); cp16(o + 16, g + 8);
        cp16(o + 32, g + 16); cp16(o + 48, g + 24);
    };

    unsigned qf[4][4];
#pragma unroll
    for (int s = 0; s < 4; s++) {
        qf[s][0] = *(const unsigned*)&Qb[(size_t)(q0 + r0) * DEPTH + 16 * s + 2 * tig];
        qf[s][1] = *(const unsigned*)&Qb[(size_t)(q0 + r1) * DEPTH + 16 * s + 2 * tig];
        qf[s][2] = *(const unsigned*)&Qb[(size_t)(q0 + r0) * DEPTH + 16 * s + 8 + 2 * tig];
        qf[s][3] = *(const unsigned*)&Qb[(size_t)(q0 + r1) * DEPTH + 16 * s + 8 + 2 * tig];
    }

    const float* mrow0 = mt + (size_t)(q0 + r0) * SEQ;
    const float* mrow1 = mt + (size_t)(q0 + r1) * SEQ;

    float m0 = -1e30f, m1 = -1e30f, l0 = 0.f, l1 = 0.f;

    // ------------------------- Pass A: stats -------------------------
    stageK(0, 0);
    cp_commit();
    int buf = 0;
    for (int kb = 0; kb < NKB; kb++) {
        cp_wait0();
        __syncthreads();
        if (kb + 1 < NKB) { stageK(kb + 1, buf ^ 1); cp_commit(); }

#pragma unroll
        for (int ch = 0; ch < 2; ch++) {
            const int k0 = kb * KBB + ch * 64;
            const int rowoff = buf * KBB + ch * 64;

            float acc[8][4];
#pragma unroll
            for (int ni = 0; ni < 8; ni++)
#pragma unroll
                for (int r = 0; r < 4; r++) acc[ni][r] = 0.f;

#pragma unroll
            for (int s = 0; s < 4; s++) {
                unsigned bf[8][2];
#pragma unroll
                for (int i = 0; i < 4; i++) {
                    unsigned addr = ks_base +
                        (unsigned)(((rowoff + (2 * i + ni_off) * 8 + mrr) * QSTR
                                    + 16 * s + kh_off) * 2);
                    ldsm_x4(bf[2 * i][0], bf[2 * i][1], bf[2 * i + 1][0], bf[2 * i + 1][1], addr);
                }
#pragma unroll
                for (int ni = 0; ni < 8; ni++) mma16(acc[ni], qf[s], bf[ni]);
            }

            if (hasmask) {
#pragma unroll
                for (int ni = 0; ni < 8; ni++) {
                    int cc = ni * 8 + 2 * tig;
                    float2 mv0 = *(const float2*)&mrow0[k0 + cc];
                    float2 mv1 = *(const float2*)&mrow1[k0 + cc];
                    acc[ni][0] += mv0.x; acc[ni][1] += mv0.y;
                    acc[ni][2] += mv1.x; acc[ni][3] += mv1.y;
                }
            }

            float rm0 = -1e30f, rm1 = -1e30f;
#pragma unroll
            for (int ni = 0; ni < 8; ni++) {
                rm0 = fmaxf(rm0, fmaxf(acc[ni][0], acc[ni][1]));
                rm1 = fmaxf(rm1, fmaxf(acc[ni][2], acc[ni][3]));
            }
            rm0 = fmaxf(rm0, __shfl_xor_sync(0xffffffffu, rm0, 1));
            rm0 = fmaxf(rm0, __shfl_xor_sync(0xffffffffu, rm0, 2));
            rm1 = fmaxf(rm1, __shfl_xor_sync(0xffffffffu, rm1, 1));
            rm1 = fmaxf(rm1, __shfl_xor_sync(0xffffffffu, rm1, 2));

            float mn0 = fmaxf(m0, rm0), mn1 = fmaxf(m1, rm1);
            float sc0 = ex2(m0 - mn0), sc1 = ex2(m1 - mn1);
            m0 = mn0; m1 = mn1;

            float ts0 = 0.f, ts1 = 0.f;
#pragma unroll
            for (int ni = 0; ni < 8; ni++) {
                ts0 += ex2(acc[ni][0] - m0) + ex2(acc[ni][1] - m0);
                ts1 += ex2(acc[ni][2] - m1) + ex2(acc[ni][3] - m1);
            }
            ts0 += __shfl_xor_sync(0xffffffffu, ts0, 1);
            ts0 += __shfl_xor_sync(0xffffffffu, ts0, 2);
            ts1 += __shfl_xor_sync(0xffffffffu, ts1, 1);
            ts1 += __shfl_xor_sync(0xffffffffu, ts1, 2);

            l0 = l0 * sc0 + ts0;
            l1 = l1 * sc1 + ts1;
        }
        __syncthreads();
        buf ^= 1;
    }

    const float z0 = m0 + lg2(l0);
    const float z1 = m1 + lg2(l1);

    // ------------------------- Pass B: write + PV -------------------------
    float cacc[8][4];
#pragma unroll
    for (int ni = 0; ni < 8; ni++)
#pragma unroll
        for (int r = 0; r < 4; r++) cacc[ni][r] = 0.f;

    stageK(0, 0); stageV(0, 0);
    cp_commit();
    buf = 0;
    for (int kb = 0; kb < NKB; kb++) {
        cp_wait0();
        __syncthreads();
        if (kb + 1 < NKB) { stageK(kb + 1, buf ^ 1); stageV(kb + 1, buf ^ 1); cp_commit(); }

#pragma unroll
        for (int ch = 0; ch < 2; ch++) {
            const int k0 = kb * KBB + ch * 64;
            const int rowoff = buf * KBB + ch * 64;

            float acc[8][4];
#pragma unroll
            for (int ni = 0; ni < 8; ni++)
#pragma unroll
                for (int r = 0; r < 4; r++) acc[ni][r] = 0.f;

#pragma unroll
            for (int s = 0; s < 4; s++) {
                unsigned bf[8][2];
#pragma unroll
                for (int i = 0; i < 4; i++) {
                    unsigned addr = ks_base +
                        (unsigned)(((rowoff + (2 * i + ni_off) * 8 + mrr) * QSTR
                                    + 16 * s + kh_off) * 2);
                    ldsm_x4(bf[2 * i][0], bf[2 * i][1], bf[2 * i + 1][0], bf[2 * i + 1][1], addr);
                }
#pragma unroll
                for (int ni = 0; ni < 8; ni++) mma16(acc[ni], qf[s], bf[ni]);
            }

            if (hasmask) {
#pragma unroll
                for (int ni = 0; ni < 8; ni++) {
                    int cc = ni * 8 + 2 * tig;
                    float2 mv0 = *(const float2*)&mrow0[k0 + cc];
                    float2 mv1 = *(const float2*)&mrow1[k0 + cc];
                    acc[ni][0] += mv0.x; acc[ni][1] += mv0.y;
                    acc[ni][2] += mv1.x; acc[ni][3] += mv1.y;
                }
            }

            unsigned pf[4][4];
#pragma unroll
            for (int ni = 0; ni < 8; ni++) {
                int cc = ni * 8 + 2 * tig;
                float p00 = ex2(acc[ni][0] - z0);
                float p01 = ex2(acc[ni][1] - z0);
                float p10 = ex2(acc[ni][2] - z1);
                float p11 = ex2(acc[ni][3] - z1);
                *(float2*)&psm[r0 * PSTR + cc] = make_float2(p00, p01);
                *(float2*)&psm[r1 * PSTR + cc] = make_float2(p10, p11);
                int sp = ni >> 1;
                if (ni & 1) { pf[sp][2] = pack2(p00, p01); pf[sp][3] = pack2(p10, p11); }
                else        { pf[sp][0] = pack2(p00, p01); pf[sp][1] = pack2(p10, p11); }
            }

#pragma unroll
            for (int s = 0; s < 4; s++) {
                unsigned vbf[8][2];
#pragma unroll
                for (int i = 0; i < 4; i++) {
                    unsigned addr = vs_base +
                        (unsigned)(((rowoff + 16 * s + kh_off + mrr) * QSTR
                                    + (2 * i + ni_off) * 8) * 2);
                    ldsm_x4_t(vbf[2 * i][0], vbf[2 * i][1], vbf[2 * i + 1][0], vbf[2 * i + 1][1], addr);
                }
#pragma unroll
                for (int ni = 0; ni < 8; ni++) mma16(cacc[ni], pf[s], vbf[ni]);
            }

            __syncthreads();
#pragma unroll
            for (int i = 0; i < 8; i++) {
                int idx = t + i * 256;
                int row = idx >> 4;
                int c4 = (idx & 15) << 2;
                float4 v = *(const float4*)&psm[row * PSTR + c4];
                *(float4*)&attnb[(size_t)(q0 + row) * SEQ + k0 + c4] = v;
            }
            __syncthreads();
        }
        buf ^= 1;
    }

    const int b = bh >> 4;
    const int hh = bh & 15;
#pragma unroll
    for (int ni = 0; ni < 8; ni++) {
        int d0 = ni * 8 + 2 * tig;
        *(unsigned*)&ctx[((size_t)b * SEQ + q0 + r0) * D_MODEL + hh * DEPTH + d0] =
            pack2(cacc[ni][0], cacc[ni][1]);
        *(unsigned*)&ctx[((size_t)b * SEQ + q0 + r1) * D_MODEL + hh * DEPTH + d0] =
            pack2(cacc[ni][2], cacc[ni][3]);
    }
}

// ---------------------------------------------------------------------------
// Inputs: v, k, q, mask, wq_w, wq_b, wk_w, wk_b, wv_w, wv_b, dense_w, dense_b
// Output: [out (B*S*D_MODEL) | attn (B*H*S*S)] fp32
// ---------------------------------------------------------------------------
extern "C" void kernel_launch(void* const* d_in, const int* in_sizes, int n_in,
                              void* d_out, int out_size)
{
    const float* v_in = (const float*)d_in[0];
    const float* k_in = (const float*)d_in[1];
    const float* q_in = (const float*)d_in[2];
    const float* mask = (const float*)d_in[3];
    const float* wq_w = (const float*)d_in[4];
    const float* wq_b = (const float*)d_in[5];
    const float* wk_w = (const float*)d_in[6];
    const float* wk_b = (const float*)d_in[7];
    const float* wv_w = (const float*)d_in[8];
    const float* wv_b = (const float*)d_in[9];
    const float* dw   = (const float*)d_in[10];
    const float* db   = (const float*)d_in[11];

    float* out  = (float*)d_out;
    float* attn = out + (size_t)BATCH * SEQ * D_MODEL;

    __half *gq, *gk, *gv, *gctx, *gxh, *gwh;
    float* gmt;
    int* gnz;
    cudaGetSymbolAddress((void**)&gq,   g_Q);
    cudaGetSymbolAddress((void**)&gk,   g_K);
    cudaGetSymbolAddress((void**)&gv,   g_V);
    cudaGetSymbolAddress((void**)&gctx, g_CTX);
    cudaGetSymbolAddress((void**)&gxh,  g_XH);
    cudaGetSymbolAddress((void**)&gwh,  g_WH);
    cudaGetSymbolAddress((void**)&gmt,  g_MT);
    cudaGetSymbolAddress((void**)&gnz,  g_NZ);

    const size_t XN = (size_t)MTOT * D_MODEL;
    const size_t WN = (size_t)D_MODEL * D_MODEL;
    __half* xh_v = gxh;
    __half* xh_k = gxh + XN;
    __half* xh_q = gxh + 2 * XN;
    __half* wh_q = gwh;
    __half* wh_k = gwh + WN;
    __half* wh_v = gwh + 2 * WN;
    __half* wh_d = gwh + 3 * WN;

    ConvJobs jobs;
    jobs.src[0] = v_in;  jobs.dst[0] = xh_v; jobs.n[0] = (int)XN;
    jobs.src[1] = k_in;  jobs.dst[1] = xh_k; jobs.n[1] = (int)XN;
    jobs.src[2] = q_in;  jobs.dst[2] = xh_q; jobs.n[2] = (int)XN;
    jobs.src[3] = wq_w;  jobs.dst[3] = wh_q; jobs.n[3] = (int)WN;
    jobs.src[4] = wk_w;  jobs.dst[4] = wh_k; jobs.n[4] = (int)WN;
    jobs.src[5] = wv_w;  jobs.dst[5] = wh_v; jobs.n[5] = (int)WN;
    jobs.src[6] = dw;    jobs.dst[6] = wh_d; jobs.n[6] = (int)WN;
    jobs.msrc = mask;
    jobs.mdst = gmt;
    jobs.mn = SEQ * SEQ;

    zero_nz<<<1, 1>>>();
    dim3 gcv(512, 1, 8);
    convert_f2h<<<gcv, 256>>>(jobs);

    const int gsmem = 6 * 128 * GSTR * (int)sizeof(__half);    // 61440
    cudaFuncSetAttribute(gemm_qkv,
                         cudaFuncAttributeMaxDynamicSharedMemorySize, gsmem);
    cudaFuncSetAttribute(gemm_dense,
                         cudaFuncAttributeMaxDynamicSharedMemorySize, gsmem);

    ProjJobs pj;
    pj.A[0] = xh_q; pj.W[0] = wh_q; pj.bias[0] = wq_b; pj.C[0] = gq; pj.oscale[0] = QSCALE;
    pj.A[1] = xh_k; pj.W[1] = wh_k; pj.bias[1] = wk_b; pj.C[1] = gk; pj.oscale[1] = 1.0f;
    pj.A[2] = xh_v; pj.W[2] = wh_v; pj.bias[2] = wv_b; pj.C[2] = gv; pj.oscale[2] = 1.0f;

    dim3 gp(D_MODEL / 128, MTOT / 128, 3);     // (8, 64, 3) = 1536 CTAs
    gemm_qkv<<<gp, 256, gsmem>>>(pj);

    const int fsmem = 4 * KBB * QSTR * (int)sizeof(__half)
                    + 128 * PSTR * (int)sizeof(float);
    cudaFuncSetAttribute(fused_attn, cudaFuncAttributeMaxDynamicSharedMemorySize, fsmem);
    dim3 gf(SEQ / BQ, BHN);
    fused_attn<<<gf, 256, fsmem>>>(gq, gk, gv, gmt, gnz, attn, gctx);

    dim3 gd(D_MODEL / 128, MTOT / 128);
    gemm_dense<<<gd, 256, gsmem>>>(gctx, wh_d, db, out);
}